// round 1
// baseline (speedup 1.0000x reference)
#include <cuda_runtime.h>
#include <cstdint>
#include <math.h>

// ---------------- problem constants ----------------
#define INV_TAU (1.0f / 0.07f)
constexpr int Bb = 16, Ll = 32, Dd = 256, Kk = 131072;
constexpr int Nn = 512;          // B*L frames
constexpr int NQ = 528;          // 512 z rows + 16 g rows
constexpr int NQP = 576;         // padded to 9*64
constexpr int BM = 64, BN = 128, BK = 32;
constexpr int NTILES = Kk / BN;  // 1024
constexpr int MTILES = NQP / BM; // 9
constexpr int MLL = Bb * (Ll - 1);  // 496 anchors

// ---------------- device scratch (no allocations allowed) ----------------
__device__ float d_Qbuf[NQP * Dd];          // prescaled queries (z/TAU, g/TAU, 0-pad)
__device__ float d_part[NQP * NTILES];      // partial lse per (row, n-tile)
__device__ float d_lseq[NQ];                // lse over queue per query row
__device__ float d_llterms[MLL];
__device__ float d_glterms[Nn];

// ---------------- helpers ----------------
__device__ __forceinline__ uint32_t f2tf(float x) {
    uint32_t r;
    asm("cvt.rna.tf32.f32 %0, %1;" : "=r"(r) : "f"(x));
    return r;
}

__device__ __forceinline__ void mma8(float4& d, const uint32_t* a, const uint32_t* b) {
    asm volatile(
        "mma.sync.aligned.m16n8k8.row.col.f32.tf32.tf32.f32 "
        "{%0,%1,%2,%3}, {%4,%5,%6,%7}, {%8,%9}, {%0,%1,%2,%3};\n"
        : "+f"(d.x), "+f"(d.y), "+f"(d.z), "+f"(d.w)
        : "r"(a[0]), "r"(a[1]), "r"(a[2]), "r"(a[3]), "r"(b[0]), "r"(b[1]));
}

// stable softplus-style: logaddexp(p, l) - p = softplus(l - p)
__device__ __forceinline__ float softplusf(float x) {
    return (x > 0.f) ? x + log1pf(expf(-x)) : log1pf(expf(x));
}

// ---------------- kernel 1: build prescaled query buffer ----------------
__global__ void k_prep(const float* __restrict__ z, const float* __restrict__ g) {
    int i = blockIdx.x * blockDim.x + threadIdx.x;   // 0 .. NQP*Dd-1
    int row = i >> 8, d = i & 255;
    float v = 0.f;
    if (row < Nn)       v = z[i] * INV_TAU;
    else if (row < NQ)  v = g[(row - Nn) * Dd + d] * INV_TAU;
    d_Qbuf[i] = v;
}

// ---------------- kernel 2: tf32 GEMM vs queue + per-tile lse ----------------
__global__ __launch_bounds__(256) void k_gemm(const float* __restrict__ mq) {
    __shared__ uint32_t As[BM][BK + 4];    // pitch 36: conflict-free frag reads
    __shared__ uint32_t Bs[BN][BK + 4];
    __shared__ float red_m[BM][4];
    __shared__ float red_s[BM][4];

    const int tid   = threadIdx.x;
    const int mtile = blockIdx.x;
    const int ntile = blockIdx.y;
    const int warp  = tid >> 5, lane = tid & 31;
    const int wm = warp >> 2, wn = warp & 3;     // 2 x 4 warp grid
    const int g8 = lane >> 2, tg = lane & 3;

    float4 acc[2][4];
#pragma unroll
    for (int mi = 0; mi < 2; mi++)
#pragma unroll
        for (int ni = 0; ni < 4; ni++)
            acc[mi][ni] = make_float4(0.f, 0.f, 0.f, 0.f);

    const float* Qb = d_Qbuf + mtile * BM * Dd;
    const float* Mb = mq + (long)ntile * BN * Dd;

    for (int kk = 0; kk < Dd; kk += BK) {
        // A tile 64x32 (2 float4 / thread)
#pragma unroll
        for (int i = 0; i < 2; i++) {
            int id = tid + i * 256;
            int r = id >> 3, c4 = id & 7;
            float4 v = *(const float4*)(Qb + r * Dd + kk + c4 * 4);
            uint4 u = make_uint4(f2tf(v.x), f2tf(v.y), f2tf(v.z), f2tf(v.w));
            *(uint4*)&As[r][c4 * 4] = u;
        }
        // B tile 128x32 (4 float4 / thread)
#pragma unroll
        for (int i = 0; i < 4; i++) {
            int id = tid + i * 256;
            int r = id >> 3, c4 = id & 7;
            float4 v = *(const float4*)(Mb + r * Dd + kk + c4 * 4);
            uint4 u = make_uint4(f2tf(v.x), f2tf(v.y), f2tf(v.z), f2tf(v.w));
            *(uint4*)&Bs[r][c4 * 4] = u;
        }
        __syncthreads();

#pragma unroll
        for (int ks = 0; ks < 4; ks++) {
            const int k0 = ks * 8;
            uint32_t a[2][4];
#pragma unroll
            for (int mi = 0; mi < 2; mi++) {
                int r = wm * 32 + mi * 16 + g8;
                a[mi][0] = As[r][k0 + tg];
                a[mi][1] = As[r + 8][k0 + tg];
                a[mi][2] = As[r][k0 + tg + 4];
                a[mi][3] = As[r + 8][k0 + tg + 4];
            }
            uint32_t b[4][2];
#pragma unroll
            for (int ni = 0; ni < 4; ni++) {
                int c = wn * 32 + ni * 8 + g8;
                b[ni][0] = Bs[c][k0 + tg];
                b[ni][1] = Bs[c][k0 + tg + 4];
            }
#pragma unroll
            for (int mi = 0; mi < 2; mi++)
#pragma unroll
                for (int ni = 0; ni < 4; ni++)
                    mma8(acc[mi][ni], a[mi], b[ni]);
        }
        __syncthreads();
    }

    // ---- epilogue: per-row (max, sumexp) over this 128-col tile ----
#pragma unroll
    for (int mi = 0; mi < 2; mi++) {
#pragma unroll
        for (int half = 0; half < 2; half++) {
            float v[8];
#pragma unroll
            for (int ni = 0; ni < 4; ni++) {
                v[2 * ni]     = half ? acc[mi][ni].z : acc[mi][ni].x;
                v[2 * ni + 1] = half ? acc[mi][ni].w : acc[mi][ni].y;
            }
            float m = v[0];
#pragma unroll
            for (int i = 1; i < 8; i++) m = fmaxf(m, v[i]);
            float s = 0.f;
#pragma unroll
            for (int i = 0; i < 8; i++) s += expf(v[i] - m);
            // reduce across the 4 lanes sharing this row (lanes differ in tg)
#pragma unroll
            for (int o = 1; o < 4; o <<= 1) {
                float om = __shfl_xor_sync(0xffffffffu, m, o);
                float os = __shfl_xor_sync(0xffffffffu, s, o);
                float nm = fmaxf(m, om);
                s = s * expf(m - nm) + os * expf(om - nm);
                m = nm;
            }
            if (tg == 0) {
                int rl = wm * 32 + mi * 16 + half * 8 + g8;
                red_m[rl][wn] = m;
                red_s[rl][wn] = s;
            }
        }
    }
    __syncthreads();

    if (tid < BM) {
        float m = red_m[tid][0], s = red_s[tid][0];
#pragma unroll
        for (int w = 1; w < 4; w++) {
            float om = red_m[tid][w], os = red_s[tid][w];
            float nm = fmaxf(m, om);
            s = s * expf(m - nm) + os * expf(om - nm);
            m = nm;
        }
        int grow = mtile * BM + tid;
        if (grow < NQ) d_part[grow * NTILES + ntile] = m + logf(s);
    }
}

// ---------------- kernel 3: reduce 1024 partial lse -> lse_q per row ----------------
__global__ void k_reduce() {
    const int row = blockIdx.x, tid = threadIdx.x;
    const float* p = d_part + row * NTILES;
    float vals[4];
    float m = -INFINITY;
#pragma unroll
    for (int i = 0; i < 4; i++) {
        vals[i] = p[tid + i * 256];
        m = fmaxf(m, vals[i]);
    }
    __shared__ float sm[256];
    sm[tid] = m;
    __syncthreads();
    for (int st = 128; st; st >>= 1) {
        if (tid < st) sm[tid] = fmaxf(sm[tid], sm[tid + st]);
        __syncthreads();
    }
    const float M = sm[0];
    __syncthreads();
    float s = 0.f;
#pragma unroll
    for (int i = 0; i < 4; i++) s += expf(vals[i] - M);
    sm[tid] = s;
    __syncthreads();
    for (int st = 128; st; st >>= 1) {
        if (tid < st) sm[tid] += sm[tid + st];
        __syncthreads();
    }
    if (tid == 0) d_lseq[row] = M + logf(sm[0]);
}

// ---------------- kernel 4: fp32 row losses (z@z.T and g@z.T parts) ----------------
__global__ void k_rows(const float* __restrict__ z) {
    __shared__ float qs[Dd];
    __shared__ float rm[256], rs[256];
    __shared__ float posbuf[Ll];
    __shared__ float s_pos;
    __shared__ float s_lse;

    const int bid = blockIdx.x, tid = threadIdx.x;
    const bool is_g = (bid >= Nn);
    const int a = bid;            // z frame index when !is_g
    const int gb = bid - Nn;      // g index when is_g

    qs[tid] = d_Qbuf[bid * Dd + tid];   // already divided by TAU
    __syncthreads();

    float m = -INFINITY, sacc = 0.f;
#pragma unroll
    for (int rep = 0; rep < 2; rep++) {
        const int j = tid + rep * 256;
        const float4* q4 = (const float4*)qs;
        const float4* z4 = (const float4*)(z + j * Dd);
        float d0 = 0.f, d1 = 0.f;
#pragma unroll 8
        for (int d = 0; d < 64; d += 2) {
            float4 aq = q4[d], bz = z4[d];
            d0 += aq.x * bz.x + aq.y * bz.y + aq.z * bz.z + aq.w * bz.w;
            float4 aq2 = q4[d + 1], bz2 = z4[d + 1];
            d1 += aq2.x * bz2.x + aq2.y * bz2.y + aq2.z * bz2.z + aq2.w * bz2.w;
        }
        const float v = d0 + d1;  // sim / TAU
        bool masked = false;
        if (is_g) {
            if ((j >> 5) == gb) { posbuf[j & 31] = v; masked = true; }
        } else {
            if (j == a) masked = true;
            else if (j == a + 1) { s_pos = v; masked = true; }
        }
        if (!masked) {
            if (v > m) { sacc = sacc * expf(m - v) + 1.f; m = v; }
            else       { sacc += expf(v - m); }
        }
    }

    rm[tid] = m; rs[tid] = sacc;
    __syncthreads();
    for (int st = 128; st; st >>= 1) {
        if (tid < st) {
            float m1 = rm[tid], s1 = rs[tid];
            float m2 = rm[tid + st], s2 = rs[tid + st];
            float nm = fmaxf(m1, m2);
            float ns;
            if (nm == -INFINITY) ns = 0.f;
            else ns = s1 * expf(m1 - nm) + s2 * expf(m2 - nm);
            rm[tid] = nm; rs[tid] = ns;
        }
        __syncthreads();
    }
    if (tid == 0) {
        const float lneg = rm[0] + logf(rs[0]);
        const float lq = d_lseq[bid];
        const float hi = fmaxf(lneg, lq), lo = fminf(lneg, lq);
        s_lse = hi + log1pf(expf(lo - hi));
    }
    __syncthreads();

    if (!is_g) {
        const int t = a & (Ll - 1);
        if (t < Ll - 1 && tid == 0) {
            d_llterms[(a >> 5) * (Ll - 1) + t] = softplusf(s_lse - s_pos);
        }
    } else {
        if (tid < Ll) {
            d_glterms[gb * Ll + tid] = softplusf(s_lse - posbuf[tid]);
        }
    }
}

// ---------------- kernel 5: deterministic final reduction ----------------
__global__ void k_final(const float* __restrict__ z, float* __restrict__ out) {
    __shared__ float sm[256];
    const int tid = threadIdx.x;

    float sll = 0.f;
    for (int i = tid; i < MLL; i += 256) sll += d_llterms[i];
    float sgl = 0.f;
    for (int i = tid; i < Nn; i += 256) sgl += d_glterms[i];
    float ssm = 0.f;
    const int total = Bb * (Ll - 1) * Dd;
    for (int i = tid; i < total; i += 256) {
        int b = i / ((Ll - 1) * Dd);
        int r = i % ((Ll - 1) * Dd);
        int t = r >> 8, d = r & 255;
        float df = z[(b * Ll + t + 1) * Dd + d] - z[(b * Ll + t) * Dd + d];
        ssm += df * df;
    }

    float Sll, Sgl, Ssm;
    sm[tid] = sll; __syncthreads();
    for (int st = 128; st; st >>= 1) { if (tid < st) sm[tid] += sm[tid + st]; __syncthreads(); }
    Sll = sm[0]; __syncthreads();
    sm[tid] = sgl; __syncthreads();
    for (int st = 128; st; st >>= 1) { if (tid < st) sm[tid] += sm[tid + st]; __syncthreads(); }
    Sgl = sm[0]; __syncthreads();
    sm[tid] = ssm; __syncthreads();
    for (int st = 128; st; st >>= 1) { if (tid < st) sm[tid] += sm[tid + st]; __syncthreads(); }
    Ssm = sm[0];

    if (tid == 0) {
        out[0] = Sll / (float)MLL + 0.5f * (Sgl / (float)Nn) + 0.1f * (Ssm / (float)MLL);
    }
}

// ---------------- launch ----------------
extern "C" void kernel_launch(void* const* d_in, const int* in_sizes, int n_in,
                              void* d_out, int out_size) {
    const float* z  = (const float*)d_in[0];   // z_t  [16,32,256]
    const float* g  = (const float*)d_in[1];   // g    [16,256]
    const float* mq = (const float*)d_in[3];   // memory_queue [131072,256]
    float* out = (float*)d_out;

    k_prep<<<NQP, 256>>>(z, g);
    dim3 grid(MTILES, NTILES);     // row-tiles fastest -> queue chunk L2 reuse
    k_gemm<<<grid, 256>>>(mq);
    k_reduce<<<NQ, 256>>>();
    k_rows<<<NQ, 256>>>(z);
    k_final<<<1, 256>>>(z, out);
}